// round 2
// baseline (speedup 1.0000x reference)
#include <cuda_runtime.h>
#include <cstdint>

// ---------------------------------------------------------------------------
// out = RMSNorm( x @ (mean_l conv_w[l])^T ) * norm_w
// x[16384,1024] f32, conv_w[20,1024,1024] f32, norm_w[1024] f32
// NOTE: harness compiles for virtual arch compute_103 -> no tcgen05/TMEM.
// Use mma.sync tf32 (sm_80 baseline) + cp.async instead.
// ---------------------------------------------------------------------------

static constexpr int M = 16384;
static constexpr int N = 1024;
static constexpr int K = 1024;
static constexpr int L = 20;

static constexpr int BM = 128;
static constexpr int BN = 256;
static constexpr int BK = 32;
static constexpr int NKIT = K / BK;       // 32
static constexpr int PAD = 36;            // smem row stride in floats (conflict-free frags)

static constexpr int A_BYTES = BM * PAD * 4;        // 18432
static constexpr int B_BYTES = BN * PAD * 4;        // 36864
static constexpr int STAGE_BYTES = A_BYTES + B_BYTES; // 55296
static constexpr int SMEM_BYTES = 2 * STAGE_BYTES;    // 110592

// Scratch (device global: allocation-free rule). Reduced weight matrix.
__device__ __align__(16) float g_W[N * K];          // 4 MB

// ---------------------------------------------------------------------------
// helpers
// ---------------------------------------------------------------------------
__device__ __forceinline__ uint32_t smem_u32(const void* p) {
    uint32_t a;
    asm("{ .reg .u64 t; cvta.to.shared.u64 t, %1; cvt.u32.u64 %0, t; }"
        : "=r"(a) : "l"(p));
    return a;
}

__device__ __forceinline__ uint32_t cvt_tf32(float f) {
    uint32_t u;
    asm("cvt.rna.tf32.f32 %0, %1;" : "=r"(u) : "f"(f));
    return u;
}

__device__ __forceinline__ void mma_tf32(float* c, const uint32_t* a, const uint32_t* b) {
    asm volatile(
        "mma.sync.aligned.m16n8k8.row.col.f32.tf32.tf32.f32 "
        "{%0,%1,%2,%3}, {%4,%5,%6,%7}, {%8,%9}, {%0,%1,%2,%3};"
        : "+f"(c[0]), "+f"(c[1]), "+f"(c[2]), "+f"(c[3])
        : "r"(a[0]), "r"(a[1]), "r"(a[2]), "r"(a[3]), "r"(b[0]), "r"(b[1]));
}

__device__ __forceinline__ void cp_async16(uint32_t dst_smem, const void* src) {
    asm volatile("cp.async.cg.shared.global [%0], [%1], 16;"
                 :: "r"(dst_smem), "l"(src));
}
__device__ __forceinline__ void cp_commit() {
    asm volatile("cp.async.commit_group;" ::: "memory");
}
template <int NN>
__device__ __forceinline__ void cp_wait() {
    asm volatile("cp.async.wait_group %0;" :: "n"(NN) : "memory");
}

// ---------------------------------------------------------------------------
// Kernel 1: W[o,i] = (1/L) * sum_l conv_w[l,o,i]
// ---------------------------------------------------------------------------
__global__ __launch_bounds__(256) void reduce_w_kernel(const float4* __restrict__ cw) {
    int idx = blockIdx.x * 256 + threadIdx.x;        // 0 .. 262143
    float4 acc = make_float4(0.f, 0.f, 0.f, 0.f);
#pragma unroll
    for (int l = 0; l < L; ++l) {
        float4 v = cw[(size_t)l * (N * K / 4) + idx];
        acc.x += v.x; acc.y += v.y; acc.z += v.z; acc.w += v.w;
    }
    const float s = 1.0f / (float)L;
    acc.x *= s; acc.y *= s; acc.z *= s; acc.w *= s;
    ((float4*)g_W)[idx] = acc;
}

// ---------------------------------------------------------------------------
// Kernel 2: tf32 mma.sync GEMM  y = x @ W^T   (y written to d_out, f32)
//   CTA 128x256x32, 8 warps at 64x64, 2-stage cp.async pipeline.
// ---------------------------------------------------------------------------
__global__ __launch_bounds__(256, 1) void gemm_tf32_kernel(const float* __restrict__ X,
                                                           float* __restrict__ Y) {
    extern __shared__ __align__(16) char smem[];
    const int tid = threadIdx.x;
    const int wid = tid >> 5;
    const int lid = tid & 31;
    const int g = lid >> 2;     // group id 0..7
    const int t = lid & 3;      // thread-in-group 0..3
    const int wm = wid >> 2;    // 0..1 -> rows of 64
    const int wn = wid & 3;     // 0..3 -> cols of 64

    const int n0 = blockIdx.x * BN;
    const int m0 = blockIdx.y * BM;

    const uint32_t sbase = smem_u32(smem);

    float acc[4][8][4];
#pragma unroll
    for (int i = 0; i < 4; ++i)
#pragma unroll
        for (int j = 0; j < 8; ++j)
#pragma unroll
            for (int q = 0; q < 4; ++q) acc[i][j][q] = 0.f;

    const float* Abase = X + (size_t)m0 * K;
    const float* Bbase = g_W + (size_t)n0 * K;

    // --- tile loader (cp.async, raw f32) ---
    auto load_tiles = [&](int kt, int stage) {
        const uint32_t sA = sbase + stage * STAGE_BYTES;
        const uint32_t sB = sA + A_BYTES;
        const float* Ak = Abase + kt * BK;
        const float* Bk = Bbase + kt * BK;
#pragma unroll
        for (int q = 0; q < 4; ++q) {           // A: 128 rows x 8 chunks
            int id = tid + q * 256;
            int row = id >> 3, s = id & 7;
            cp_async16(sA + (uint32_t)(row * PAD + s * 4) * 4,
                       Ak + (size_t)row * K + s * 4);
        }
#pragma unroll
        for (int q = 0; q < 8; ++q) {           // B: 256 rows x 8 chunks
            int id = tid + q * 256;
            int row = id >> 3, s = id & 7;
            cp_async16(sB + (uint32_t)(row * PAD + s * 4) * 4,
                       Bk + (size_t)row * K + s * 4);
        }
        cp_commit();
    };

    load_tiles(0, 0);

#pragma unroll 1
    for (int kt = 0; kt < NKIT; ++kt) {
        if (kt + 1 < NKIT) load_tiles(kt + 1, (kt + 1) & 1);
        if (kt + 1 < NKIT) cp_wait<1>(); else cp_wait<0>();
        __syncthreads();

        const float* As = (const float*)(smem + (kt & 1) * STAGE_BYTES);
        const float* Bs = (const float*)(smem + (kt & 1) * STAGE_BYTES + A_BYTES);

#pragma unroll
        for (int ks = 0; ks < 4; ++ks) {
            const int c0 = ks * 8 + t;
            uint32_t a[4][4], b[8][2];
#pragma unroll
            for (int i = 0; i < 4; ++i) {
                int r = wm * 64 + i * 16 + g;
                a[i][0] = cvt_tf32(As[r * PAD + c0]);
                a[i][1] = cvt_tf32(As[(r + 8) * PAD + c0]);
                a[i][2] = cvt_tf32(As[r * PAD + c0 + 4]);
                a[i][3] = cvt_tf32(As[(r + 8) * PAD + c0 + 4]);
            }
#pragma unroll
            for (int j = 0; j < 8; ++j) {
                int n = wn * 64 + j * 8 + g;
                b[j][0] = cvt_tf32(Bs[n * PAD + c0]);
                b[j][1] = cvt_tf32(Bs[n * PAD + c0 + 4]);
            }
#pragma unroll
            for (int i = 0; i < 4; ++i)
#pragma unroll
                for (int j = 0; j < 8; ++j)
                    mma_tf32(acc[i][j], a[i], b[j]);
        }
        __syncthreads();
    }

    // --- epilogue: write f32 result ---
#pragma unroll
    for (int i = 0; i < 4; ++i) {
        int row = m0 + wm * 64 + i * 16 + g;
#pragma unroll
        for (int j = 0; j < 8; ++j) {
            int col = n0 + wn * 64 + j * 8 + t * 2;
            float2 v0 = make_float2(acc[i][j][0], acc[i][j][1]);
            float2 v1 = make_float2(acc[i][j][2], acc[i][j][3]);
            *(float2*)(Y + (size_t)row * N + col) = v0;
            *(float2*)(Y + (size_t)(row + 8) * N + col) = v1;
        }
    }
}

// ---------------------------------------------------------------------------
// Kernel 3: in-place RMSNorm over rows of 1024 of d_out
// ---------------------------------------------------------------------------
__global__ __launch_bounds__(256) void rmsnorm_kernel(const float* __restrict__ nw,
                                                      float* __restrict__ out) {
    __shared__ float red[8];
    const int row = blockIdx.x;
    const int tt = threadIdx.x;
    float4* y4 = (float4*)(out + (size_t)row * N);
    float4 v = y4[tt];
    float ss = v.x * v.x + v.y * v.y + v.z * v.z + v.w * v.w;
#pragma unroll
    for (int o = 16; o; o >>= 1) ss += __shfl_xor_sync(0xFFFFFFFFu, ss, o);
    if ((tt & 31) == 0) red[tt >> 5] = ss;
    __syncthreads();
    float tot = red[0] + red[1] + red[2] + red[3] +
                red[4] + red[5] + red[6] + red[7];
    float sc = rsqrtf(tot * (1.0f / (float)N) + 1e-6f);
    float4 w = ((const float4*)nw)[tt];
    float4 o4 = make_float4(v.x * sc * w.x, v.y * sc * w.y,
                            v.z * sc * w.z, v.w * sc * w.w);
    y4[tt] = o4;
}

// ---------------------------------------------------------------------------
// Launch
// ---------------------------------------------------------------------------
extern "C" void kernel_launch(void* const* d_in, const int* in_sizes, int n_in,
                              void* d_out, int out_size) {
    (void)in_sizes; (void)n_in; (void)out_size;
    const float* x  = (const float*)d_in[0];
    const float* cw = (const float*)d_in[1];
    const float* nw = (const float*)d_in[2];
    float* out = (float*)d_out;

    cudaFuncSetAttribute(gemm_tf32_kernel,
                         cudaFuncAttributeMaxDynamicSharedMemorySize, SMEM_BYTES);

    reduce_w_kernel<<<(N * K / 4) / 256, 256>>>((const float4*)cw);
    gemm_tf32_kernel<<<dim3(N / BN, M / BM), 256, SMEM_BYTES>>>(x, out);
    rmsnorm_kernel<<<M, 256>>>(nw, out);
}